// round 2
// baseline (speedup 1.0000x reference)
#include <cuda_runtime.h>
#include <math.h>

#define BB   2
#define TT   2048
#define DIM  2048
#define NH   16
#define HD   128
#define MTOT (BB*TT)
#define SCALE_QK 0.08838834764831843f
#define SOFTCAP 30.0f

__device__ float g_xn[MTOT * DIM];
__device__ float g_q [MTOT * DIM];
__device__ float g_k [MTOT * DIM];
__device__ float g_v [MTOT * DIM];
__device__ float g_at[MTOT * DIM];
__device__ float g_op[MTOT * DIM];
__device__ float g_gl[MTOT * DIM];

__device__ __forceinline__ void fma2(unsigned long long &c,
                                     unsigned long long a,
                                     unsigned long long b) {
    asm("fma.rn.f32x2 %0, %1, %2, %0;" : "+l"(c) : "l"(a), "l"(b));
}
__device__ __forceinline__ float f2lo(unsigned long long v) {
    return __uint_as_float((unsigned int)(v & 0xFFFFFFFFull));
}
__device__ __forceinline__ float f2hi(unsigned long long v) {
    return __uint_as_float((unsigned int)(v >> 32));
}

// ------------------------------- RMSNorm -------------------------------------
__global__ __launch_bounds__(256)
void rmsnorm_kernel(const float* __restrict__ x, const float* __restrict__ w)
{
    const int row = blockIdx.x;
    const int tid = threadIdx.x;
    const float4* xr = (const float4*)(x + row * DIM);
    float4 v0 = xr[tid];
    float4 v1 = xr[tid + 256];
    float s = v0.x*v0.x + v0.y*v0.y + v0.z*v0.z + v0.w*v0.w
            + v1.x*v1.x + v1.y*v1.y + v1.z*v1.z + v1.w*v1.w;
    #pragma unroll
    for (int o = 16; o > 0; o >>= 1) s += __shfl_xor_sync(0xffffffffu, s, o);
    __shared__ float red[8];
    if ((tid & 31) == 0) red[tid >> 5] = s;
    __syncthreads();
    float tot = red[0]+red[1]+red[2]+red[3]+red[4]+red[5]+red[6]+red[7];
    float r = rsqrtf(tot * (1.0f / (float)DIM) + 1e-6f);
    const float4* wr = (const float4*)w;
    float4 w0 = wr[tid], w1 = wr[tid + 256];
    float4* yr = (float4*)(g_xn + row * DIM);
    yr[tid]       = make_float4(v0.x*r*w0.x, v0.y*r*w0.y, v0.z*r*w0.z, v0.w*r*w0.w);
    yr[tid + 256] = make_float4(v1.x*r*w1.x, v1.y*r*w1.y, v1.z*r*w1.z, v1.w*r*w1.w);
}

// --------------------- SGEMM:  C[M,N] = A[M,K] * B[N,K]^T ---------------------
__global__ __launch_bounds__(256, 2)
void sgemm_tn_kernel(const float* __restrict__ A, const float* __restrict__ B,
                     float* __restrict__ C, int M, int N, int K)
{
    __shared__ float As [16][132];   // As[k][m]
    __shared__ float Bs2[16][260];   // Bs2[k][2n] duplicated

    const int tid = threadIdx.x;
    const int tx = tid & 15, ty = tid >> 4;
    const int mBase = ty * 8, nBase = tx * 8;
    const int lrow = tid >> 2;
    const int lk   = (tid & 3) * 4;

    const float* Ab = A + (blockIdx.y * 128 + lrow) * K + lk;
    const float* Bb = B + (blockIdx.x * 128 + lrow) * K + lk;

    unsigned long long acc[4][8];
    #pragma unroll
    for (int i = 0; i < 4; i++)
        #pragma unroll
        for (int j = 0; j < 8; j++) acc[i][j] = 0ull;

    for (int kt = 0; kt < K; kt += 16) {
        float4 a0 = *(const float4*)(Ab + kt);
        float4 a1 = *(const float4*)(Ab + 64 * K + kt);
        float4 b0 = *(const float4*)(Bb + kt);
        float4 b1 = *(const float4*)(Bb + 64 * K + kt);
        __syncthreads();
        As[lk+0][lrow]    = a0.x; As[lk+1][lrow]    = a0.y;
        As[lk+2][lrow]    = a0.z; As[lk+3][lrow]    = a0.w;
        As[lk+0][lrow+64] = a1.x; As[lk+1][lrow+64] = a1.y;
        As[lk+2][lrow+64] = a1.z; As[lk+3][lrow+64] = a1.w;
        *(float2*)&Bs2[lk+0][2*lrow]      = make_float2(b0.x, b0.x);
        *(float2*)&Bs2[lk+1][2*lrow]      = make_float2(b0.y, b0.y);
        *(float2*)&Bs2[lk+2][2*lrow]      = make_float2(b0.z, b0.z);
        *(float2*)&Bs2[lk+3][2*lrow]      = make_float2(b0.w, b0.w);
        *(float2*)&Bs2[lk+0][2*(lrow+64)] = make_float2(b1.x, b1.x);
        *(float2*)&Bs2[lk+1][2*(lrow+64)] = make_float2(b1.y, b1.y);
        *(float2*)&Bs2[lk+2][2*(lrow+64)] = make_float2(b1.z, b1.z);
        *(float2*)&Bs2[lk+3][2*(lrow+64)] = make_float2(b1.w, b1.w);
        __syncthreads();

        #pragma unroll
        for (int kk = 0; kk < 16; kk++) {
            ulonglong2 A0 = *(const ulonglong2*)&As[kk][mBase];
            ulonglong2 A1 = *(const ulonglong2*)&As[kk][mBase + 4];
            const ulonglong2* bp = (const ulonglong2*)&Bs2[kk][2 * nBase];
            ulonglong2 B0 = bp[0], B1 = bp[1], B2 = bp[2], B3 = bp[3];
            unsigned long long av[4] = {A0.x, A0.y, A1.x, A1.y};
            unsigned long long bv[8] = {B0.x, B0.y, B1.x, B1.y,
                                        B2.x, B2.y, B3.x, B3.y};
            #pragma unroll
            for (int i = 0; i < 4; i++)
                #pragma unroll
                for (int j = 0; j < 8; j++)
                    fma2(acc[i][j], av[i], bv[j]);
        }
    }

    float* Cb = C + (blockIdx.y * 128 + mBase) * N + blockIdx.x * 128 + nBase;
    #pragma unroll
    for (int mp = 0; mp < 4; mp++) {
        float* r0 = Cb + (2 * mp) * N;
        float* r1 = r0 + N;
        *(float4*)(r0)     = make_float4(f2lo(acc[mp][0]), f2lo(acc[mp][1]),
                                         f2lo(acc[mp][2]), f2lo(acc[mp][3]));
        *(float4*)(r0 + 4) = make_float4(f2lo(acc[mp][4]), f2lo(acc[mp][5]),
                                         f2lo(acc[mp][6]), f2lo(acc[mp][7]));
        *(float4*)(r1)     = make_float4(f2hi(acc[mp][0]), f2hi(acc[mp][1]),
                                         f2hi(acc[mp][2]), f2hi(acc[mp][3]));
        *(float4*)(r1 + 4) = make_float4(f2hi(acc[mp][4]), f2hi(acc[mp][5]),
                                         f2hi(acc[mp][6]), f2hi(acc[mp][7]));
    }
}

// ------------------ causal softcapped flash attention (BQ=BK=64) --------------
#define ATT_SMEM_FLOATS (128*132 + 128*66 + 64*132 + 64*132)
#define ATT_SMEM_BYTES  (ATT_SMEM_FLOATS * 4)

__global__ __launch_bounds__(256)
void attn_kernel()
{
    extern __shared__ float sm[];
    float* Qs2 = sm;                 // [d][2m] dup, stride 132
    float* Ks  = sm + 128 * 132;     // [d][n],      stride 66
    float* Vs  = Ks + 128 * 66;      // [k][d],      stride 132
    float* Ps2 = Vs + 64 * 132;      // [k][2m] dup, stride 132

    const int tid = threadIdx.x;
    const int tx = tid & 15, ty = tid >> 4;
    const int qt = (int)gridDim.x - 1 - (int)blockIdx.x;   // heavy tiles first
    const int h  = blockIdx.y;
    const int b  = blockIdx.z;

    const float* Qb = g_q + (size_t)(b * TT + qt * 64) * DIM + h * HD;
    const float* Kb = g_k + (size_t)(b * TT) * DIM + h * HD;
    const float* Vb = g_v + (size_t)(b * TT) * DIM + h * HD;

    #pragma unroll
    for (int it = 0; it < 8; it++) {
        int idx = tid + it * 256;
        int m = idx >> 5, d0 = (idx & 31) * 4;
        float4 q = *(const float4*)(Qb + m * DIM + d0);
        *(float2*)&Qs2[(d0+0)*132 + 2*m] = make_float2(q.x, q.x);
        *(float2*)&Qs2[(d0+1)*132 + 2*m] = make_float2(q.y, q.y);
        *(float2*)&Qs2[(d0+2)*132 + 2*m] = make_float2(q.z, q.z);
        *(float2*)&Qs2[(d0+3)*132 + 2*m] = make_float2(q.w, q.w);
    }

    unsigned long long Od[4][4];
    #pragma unroll
    for (int i = 0; i < 4; i++)
        #pragma unroll
        for (int j = 0; j < 4; j++) Od[i][j] = 0ull;
    float den[4] = {0.f, 0.f, 0.f, 0.f};

    for (int kt = 0; kt <= qt; kt++) {
        __syncthreads();
        #pragma unroll
        for (int it = 0; it < 8; it++) {
            int idx = tid + it * 256;
            int n = idx >> 5, d0 = (idx & 31) * 4;
            float4 kv = *(const float4*)(Kb + (size_t)(kt * 64 + n) * DIM + d0);
            Ks[(d0+0)*66 + n] = kv.x;
            Ks[(d0+1)*66 + n] = kv.y;
            Ks[(d0+2)*66 + n] = kv.z;
            Ks[(d0+3)*66 + n] = kv.w;
            float4 vv = *(const float4*)(Vb + (size_t)(kt * 64 + n) * DIM + d0);
            *(float4*)&Vs[n * 132 + d0] = vv;
        }
        __syncthreads();

        unsigned long long S[4][2];
        #pragma unroll
        for (int i = 0; i < 4; i++) { S[i][0] = 0ull; S[i][1] = 0ull; }
        #pragma unroll 8
        for (int d = 0; d < 128; d++) {
            ulonglong2 qa = *(const ulonglong2*)&Qs2[d * 132 + 8 * ty];
            ulonglong2 qb = *(const ulonglong2*)&Qs2[d * 132 + 8 * ty + 4];
            unsigned long long k0 = *(const unsigned long long*)&Ks[d * 66 + 4 * tx];
            unsigned long long k1 = *(const unsigned long long*)&Ks[d * 66 + 4 * tx + 2];
            unsigned long long qv[4] = {qa.x, qa.y, qb.x, qb.y};
            #pragma unroll
            for (int i = 0; i < 4; i++) {
                fma2(S[i][0], qv[i], k0);
                fma2(S[i][1], qv[i], k1);
            }
        }

        const bool diag = (kt == qt);
        #pragma unroll
        for (int i = 0; i < 4; i++) {
            const int m = ty * 4 + i;
            const int qglob = qt * 64 + m;
            float rs = 0.f;
            #pragma unroll
            for (int jp = 0; jp < 2; jp++) {
                const int n = tx * 4 + jp * 2;
                float slo = f2lo(S[i][jp]) * SCALE_QK;
                float shi = f2hi(S[i][jp]) * SCALE_QK;
                float plo = __expf(SOFTCAP * tanhf(slo * (1.0f / SOFTCAP)));
                float phi = __expf(SOFTCAP * tanhf(shi * (1.0f / SOFTCAP)));
                if (diag) {
                    if (kt * 64 + n     > qglob) plo = 0.f;
                    if (kt * 64 + n + 1 > qglob) phi = 0.f;
                }
                rs += plo + phi;
                *(float2*)&Ps2[(n    ) * 132 + 2 * m] = make_float2(plo, plo);
                *(float2*)&Ps2[(n + 1) * 132 + 2 * m] = make_float2(phi, phi);
            }
            rs += __shfl_xor_sync(0xffffffffu, rs, 1);
            rs += __shfl_xor_sync(0xffffffffu, rs, 2);
            rs += __shfl_xor_sync(0xffffffffu, rs, 4);
            rs += __shfl_xor_sync(0xffffffffu, rs, 8);
            den[i] += rs;
        }
        __syncthreads();

        #pragma unroll 4
        for (int k = 0; k < 64; k++) {
            ulonglong2 pa = *(const ulonglong2*)&Ps2[k * 132 + 8 * ty];
            ulonglong2 pb = *(const ulonglong2*)&Ps2[k * 132 + 8 * ty + 4];
            ulonglong2 v0 = *(const ulonglong2*)&Vs[k * 132 + 8 * tx];
            ulonglong2 v1 = *(const ulonglong2*)&Vs[k * 132 + 8 * tx + 4];
            unsigned long long pv[4] = {pa.x, pa.y, pb.x, pb.y};
            unsigned long long vv[4] = {v0.x, v0.y, v1.x, v1.y};
            #pragma unroll
            for (int i = 0; i < 4; i++)
                #pragma unroll
                for (int j = 0; j < 4; j++)
                    fma2(Od[i][j], pv[i], vv[j]);
        }
    }

    float* Ob = g_at + (size_t)(b * TT + qt * 64 + ty * 4) * DIM + h * HD + tx * 8;
    #pragma unroll
    for (int i = 0; i < 4; i++) {
        float r = 1.0f / den[i];
        *(float4*)(Ob + i * DIM)     = make_float4(f2lo(Od[i][0]) * r, f2hi(Od[i][0]) * r,
                                                   f2lo(Od[i][1]) * r, f2hi(Od[i][1]) * r);
        *(float4*)(Ob + i * DIM + 4) = make_float4(f2lo(Od[i][2]) * r, f2hi(Od[i][2]) * r,
                                                   f2lo(Od[i][3]) * r, f2hi(Od[i][3]) * r);
    }
}

// ---------------------------- gate + residual blend ---------------------------
__global__ __launch_bounds__(256)
void blend_kernel(const float* __restrict__ x, const float* __restrict__ gb,
                  float* __restrict__ out)
{
    const int i4 = blockIdx.x * 256 + threadIdx.x;
    const int col4 = i4 & 511;
    float4 xv = ((const float4*)x)[i4];
    float4 ov = ((const float4*)g_op)[i4];
    float4 gv = ((const float4*)g_gl)[i4];
    float4 bv = ((const float4*)gb)[col4];
    float a0 = 1.0f / (1.0f + __expf(-(gv.x + bv.x)));
    float a1 = 1.0f / (1.0f + __expf(-(gv.y + bv.y)));
    float a2 = 1.0f / (1.0f + __expf(-(gv.z + bv.z)));
    float a3 = 1.0f / (1.0f + __expf(-(gv.w + bv.w)));
    float4 r;
    r.x = xv.x + a0 * (ov.x - xv.x);
    r.y = xv.y + a1 * (ov.y - xv.y);
    r.z = xv.z + a2 * (ov.z - xv.z);
    r.w = xv.w + a3 * (ov.w - xv.w);
    ((float4*)out)[i4] = r;
}

// ----------------------------------- launch -----------------------------------
extern "C" void kernel_launch(void* const* d_in, const int* in_sizes, int n_in,
                              void* d_out, int out_size)
{
    (void)in_sizes; (void)n_in; (void)out_size;
    const float* x   = (const float*)d_in[0];
    const float* Wq  = (const float*)d_in[2];
    const float* Wk  = (const float*)d_in[3];
    const float* Wv  = (const float*)d_in[4];
    const float* Wo  = (const float*)d_in[5];
    const float* lnw = (const float*)d_in[6];
    const float* gW  = (const float*)d_in[7];
    const float* gb  = (const float*)d_in[8];
    float* out = (float*)d_out;

    static int smem_set = 0;
    if (!smem_set) {
        cudaFuncSetAttribute(attn_kernel,
                             cudaFuncAttributeMaxDynamicSharedMemorySize,
                             ATT_SMEM_BYTES);
        smem_set = 1;
    }

    void *pxn, *pq, *pk, *pv, *pat, *pop, *pgl;
    cudaGetSymbolAddress(&pxn, g_xn);
    cudaGetSymbolAddress(&pq,  g_q);
    cudaGetSymbolAddress(&pk,  g_k);
    cudaGetSymbolAddress(&pv,  g_v);
    cudaGetSymbolAddress(&pat, g_at);
    cudaGetSymbolAddress(&pop, g_op);
    cudaGetSymbolAddress(&pgl, g_gl);

    dim3 gGemm(DIM / 128, MTOT / 128);   // (16, 32)

    rmsnorm_kernel<<<MTOT, 256>>>(x, lnw);

    sgemm_tn_kernel<<<gGemm, 256>>>((const float*)pxn, Wq, (float*)pq, MTOT, DIM, DIM);
    sgemm_tn_kernel<<<gGemm, 256>>>((const float*)pxn, Wk, (float*)pk, MTOT, DIM, DIM);
    sgemm_tn_kernel<<<gGemm, 256>>>((const float*)pxn, Wv, (float*)pv, MTOT, DIM, DIM);
    sgemm_tn_kernel<<<gGemm, 256>>>(x, gW, (float*)pgl, MTOT, DIM, DIM);

    dim3 gAttn(TT / 64, NH, BB);         // (32, 16, 2)
    attn_kernel<<<gAttn, 256, ATT_SMEM_BYTES>>>();

    sgemm_tn_kernel<<<gGemm, 256>>>((const float*)pat, Wo, (float*)pop, MTOT, DIM, DIM);

    blend_kernel<<<(MTOT * DIM / 4) / 256, 256>>>(x, gb, out);
}

// round 5
// speedup vs baseline: 3.6979x; 3.6979x over previous
#include <cuda_runtime.h>
#include <cuda_bf16.h>
#include <math.h>
#include <stdint.h>

#define BB   2
#define TT   2048
#define DIM  2048
#define NH   16
#define HD   128
#define MTOT (BB*TT)
#define K3   6144
#define SCALE_QK 0.08838834764831843f
#define SOFTCAP 30.0f

// ---------------- scratch ----------------
__device__ float g_q [MTOT * DIM];
__device__ float g_k [MTOT * DIM];
__device__ float g_v [MTOT * DIM];
__device__ float g_at[MTOT * DIM];
__device__ float g_op[MTOT * DIM];
__device__ float g_gl[MTOT * DIM];
__device__ __nv_bfloat16 g_xn3[(size_t)MTOT * K3];
__device__ __nv_bfloat16 g_x3 [(size_t)MTOT * K3];
__device__ __nv_bfloat16 g_at3[(size_t)MTOT * K3];
__device__ __nv_bfloat16 g_w3[5][(size_t)DIM * K3];

// ---------------- helpers ----------------
__device__ __forceinline__ uint32_t smem_u32(const void* p) {
    uint32_t a;
    asm("{ .reg .u64 t; cvta.to.shared.u64 t, %1; cvt.u32.u64 %0, t; }" : "=r"(a) : "l"(p));
    return a;
}

#define LDSM_X4(r0, r1, r2, r3, a) \
    asm volatile("ldmatrix.sync.aligned.m8n8.x4.shared.b16 {%0,%1,%2,%3}, [%4];" \
        : "=r"(r0), "=r"(r1), "=r"(r2), "=r"(r3) : "r"(a))
#define MMA_BF16(c, a0, a1, a2, a3, b0, b1) \
    asm volatile("mma.sync.aligned.m16n8k16.row.col.f32.bf16.bf16.f32 " \
        "{%0,%1,%2,%3}, {%4,%5,%6,%7}, {%8,%9}, {%0,%1,%2,%3};" \
        : "+f"((c)[0]), "+f"((c)[1]), "+f"((c)[2]), "+f"((c)[3]) \
        : "r"(a0), "r"(a1), "r"(a2), "r"(a3), "r"(b0), "r"(b1))

__device__ __forceinline__ void fma2(unsigned long long &c, unsigned long long a, unsigned long long b) {
    asm("fma.rn.f32x2 %0, %1, %2, %0;" : "+l"(c) : "l"(a), "l"(b));
}
__device__ __forceinline__ float f2lo(unsigned long long v) { return __uint_as_float((unsigned)(v & 0xFFFFFFFFull)); }
__device__ __forceinline__ float f2hi(unsigned long long v) { return __uint_as_float((unsigned)(v >> 32)); }

__device__ __forceinline__ void bsplit(float v, unsigned short &h, unsigned short &l) {
    __nv_bfloat16 hb = __float2bfloat16_rn(v);
    __nv_bfloat16 lb = __float2bfloat16_rn(v - __bfloat162float(hb));
    h = __bfloat16_as_ushort(hb);
    l = __bfloat16_as_ushort(lb);
}

// ------------- RMSNorm fused with bf16 split ([hi|hi|lo]) -------------
__global__ __launch_bounds__(256)
void rmsnorm_split_kernel(const float* __restrict__ x, const float* __restrict__ w)
{
    const int row = blockIdx.x;
    const int tid = threadIdx.x;
    const float4* xr = (const float4*)(x + (size_t)row * DIM);
    float4 v0 = xr[tid];
    float4 v1 = xr[tid + 256];
    float s = v0.x*v0.x + v0.y*v0.y + v0.z*v0.z + v0.w*v0.w
            + v1.x*v1.x + v1.y*v1.y + v1.z*v1.z + v1.w*v1.w;
    #pragma unroll
    for (int o = 16; o > 0; o >>= 1) s += __shfl_xor_sync(0xffffffffu, s, o);
    __shared__ float red[8];
    if ((tid & 31) == 0) red[tid >> 5] = s;
    __syncthreads();
    float tot = red[0]+red[1]+red[2]+red[3]+red[4]+red[5]+red[6]+red[7];
    float r = rsqrtf(tot * (1.0f / (float)DIM) + 1e-6f);
    const float4* wr = (const float4*)w;
    float4 w0 = wr[tid], w1 = wr[tid + 256];
    float y[8] = { v0.x*r*w0.x, v0.y*r*w0.y, v0.z*r*w0.z, v0.w*r*w0.w,
                   v1.x*r*w1.x, v1.y*r*w1.y, v1.z*r*w1.z, v1.w*r*w1.w };
    unsigned short* ob = (unsigned short*)g_xn3 + (size_t)row * K3;
    #pragma unroll
    for (int half = 0; half < 2; half++) {
        unsigned short h[4], l[4];
        bsplit(y[half*4+0], h[0], l[0]); bsplit(y[half*4+1], h[1], l[1]);
        bsplit(y[half*4+2], h[2], l[2]); bsplit(y[half*4+3], h[3], l[3]);
        ushort4 hs = make_ushort4(h[0], h[1], h[2], h[3]);
        ushort4 ls = make_ushort4(l[0], l[1], l[2], l[3]);
        int c = (tid + half * 256) * 4;
        *(ushort4*)(ob + c)        = hs;
        *(ushort4*)(ob + c + 2048) = hs;
        *(ushort4*)(ob + c + 4096) = ls;
    }
}

// ------------- split conversion: [R,2048] fp32 -> [R,6144] bf16 -------------
// modeA=1: [hi|hi|lo]   modeA=0: [hi|lo|hi]
__global__ __launch_bounds__(256)
void convert_split_kernel(const float* __restrict__ in, __nv_bfloat16* __restrict__ out, int modeA)
{
    int idx = blockIdx.x * 256 + threadIdx.x;
    float4 v = ((const float4*)in)[idx];
    int r = idx >> 9, c = (idx & 511) * 4;
    unsigned short h[4], l[4];
    bsplit(v.x, h[0], l[0]); bsplit(v.y, h[1], l[1]);
    bsplit(v.z, h[2], l[2]); bsplit(v.w, h[3], l[3]);
    ushort4 hs = make_ushort4(h[0], h[1], h[2], h[3]);
    ushort4 ls = make_ushort4(l[0], l[1], l[2], l[3]);
    unsigned short* ob = (unsigned short*)out + (size_t)r * K3 + c;
    *(ushort4*)(ob)        = hs;
    *(ushort4*)(ob + 2048) = modeA ? hs : ls;
    *(ushort4*)(ob + 4096) = modeA ? ls : hs;
}

// ------------- HMMA bf16 GEMM: C[M,2048] = A'[M,6144] * B'[2048,6144]^T -------------
#define BM 128
#define BN 128
#define BK 64
#define GSTAGES 3
#define NCHUNK (K3 / BK)                    // 96
#define CHUNK_BYTES (BM*128 + BN*128)       // 32768
#define GEMM_SMEM (GSTAGES * CHUNK_BYTES + 1024)

__global__ __launch_bounds__(256, 1)
void mma_gemm_kernel(const __nv_bfloat16* __restrict__ A,
                     const __nv_bfloat16* __restrict__ B,
                     float* __restrict__ C, int N)
{
    extern __shared__ char dynsm[];
    const uint32_t sb = (smem_u32(dynsm) + 1023u) & ~1023u;
    const int tid = threadIdx.x;
    const int w = tid >> 5, lane = tid & 31;
    const int wm = (w >> 2) * 64, wn = (w & 3) * 32;

    const int mBase = blockIdx.y * BM;
    const int nBase = blockIdx.x * BN;
    const __nv_bfloat16* Ab = A + (size_t)mBase * K3;
    const __nv_bfloat16* Bb = B + (size_t)nBase * K3;

    float acc[4][4][4];
    #pragma unroll
    for (int i = 0; i < 4; i++)
        #pragma unroll
        for (int j = 0; j < 4; j++)
            #pragma unroll
            for (int q = 0; q < 4; q++) acc[i][j][q] = 0.f;

    auto load_chunk = [&](int c, int stage) {
        uint32_t abase = sb + stage * CHUNK_BYTES;
        uint32_t bbase = abase + BM * 128;
        #pragma unroll
        for (int t = 0; t < 8; t++) {
            int o = tid + t * 256;
            const __nv_bfloat16* src;
            uint32_t base;
            int row, c16;
            if (o < 1024) {
                row = o >> 3; c16 = o & 7;
                src = Ab + (size_t)row * K3 + c * 64 + c16 * 8;
                base = abase;
            } else {
                int ob = o - 1024;
                row = ob >> 3; c16 = ob & 7;
                src = Bb + (size_t)row * K3 + c * 64 + c16 * 8;
                base = bbase;
            }
            uint32_t off = (uint32_t)(row * 128 + c16 * 16);
            uint32_t dst = base + (off ^ ((off >> 3) & 0x70));
            asm volatile("cp.async.cg.shared.global [%0], [%1], 16;" :: "r"(dst), "l"(src) : "memory");
        }
        asm volatile("cp.async.commit_group;" ::: "memory");
    };

    load_chunk(0, 0);
    load_chunk(1, 1);

    // per-lane ldmatrix address components
    const int r8 = lane & 7;
    const int mi = lane >> 3;
    const int rowadd = r8 + (mi & 1) * 8;
    const int colmi = (mi >> 1) * 16;

    #pragma unroll 1
    for (int c = 0; c < NCHUNK; c++) {
        asm volatile("cp.async.wait_group %0;" :: "n"(1));
        __syncthreads();
        if (c + 2 < NCHUNK) load_chunk(c + 2, (c + 2) % GSTAGES);
        else asm volatile("cp.async.commit_group;" ::: "memory");

        uint32_t abase = sb + (c % GSTAGES) * CHUNK_BYTES;
        uint32_t bbase = abase + BM * 128;

        #pragma unroll
        for (int s = 0; s < 4; s++) {
            const int colb = s * 32 + colmi;
            uint32_t af[4][4];
            #pragma unroll
            for (int i = 0; i < 4; i++) {
                uint32_t off = (uint32_t)((wm + i * 16 + rowadd) * 128 + colb);
                uint32_t addr = abase + (off ^ ((off >> 3) & 0x70));
                LDSM_X4(af[i][0], af[i][1], af[i][2], af[i][3], addr);
            }
            uint32_t bf[2][4];
            #pragma unroll
            for (int j = 0; j < 2; j++) {
                uint32_t off = (uint32_t)((wn + j * 16 + rowadd) * 128 + colb);
                uint32_t addr = bbase + (off ^ ((off >> 3) & 0x70));
                LDSM_X4(bf[j][0], bf[j][1], bf[j][2], bf[j][3], addr);
            }
            #pragma unroll
            for (int i = 0; i < 4; i++)
                #pragma unroll
                for (int j = 0; j < 2; j++)
                    #pragma unroll
                    for (int ns = 0; ns < 2; ns++)
                        MMA_BF16(acc[i][j * 2 + ns],
                                 af[i][0], af[i][1], af[i][2], af[i][3],
                                 bf[j][ns], bf[j][2 + ns]);
        }
    }

    // epilogue
    const int gid = lane >> 2, ctg = lane & 3;
    float* Cw = C + (size_t)(mBase + wm + gid) * N + nBase + wn + ctg * 2;
    #pragma unroll
    for (int i = 0; i < 4; i++)
        #pragma unroll
        for (int jn = 0; jn < 4; jn++) {
            float* p = Cw + (size_t)(i * 16) * N + jn * 8;
            *(float2*)p             = make_float2(acc[i][jn][0], acc[i][jn][1]);
            *(float2*)(p + 8 * N)   = make_float2(acc[i][jn][2], acc[i][jn][3]);
        }
}

// ------------- causal softcapped flash attention (fp32x2, BQ=BK=64) -------------
#define ATT_SMEM_FLOATS (128*132 + 128*66 + 64*132 + 64*132)
#define ATT_SMEM_BYTES  (ATT_SMEM_FLOATS * 4)

__global__ __launch_bounds__(256)
void attn_kernel()
{
    extern __shared__ float sm[];
    float* Qs2 = sm;
    float* Ks  = sm + 128 * 132;
    float* Vs  = Ks + 128 * 66;
    float* Ps2 = Vs + 64 * 132;

    const int tid = threadIdx.x;
    const int tx = tid & 15, ty = tid >> 4;
    const int qt = (int)gridDim.x - 1 - (int)blockIdx.x;
    const int h  = blockIdx.y;
    const int b  = blockIdx.z;

    const float* Qb = g_q + (size_t)(b * TT + qt * 64) * DIM + h * HD;
    const float* Kb = g_k + (size_t)(b * TT) * DIM + h * HD;
    const float* Vb = g_v + (size_t)(b * TT) * DIM + h * HD;

    #pragma unroll
    for (int it = 0; it < 8; it++) {
        int idx = tid + it * 256;
        int m = idx >> 5, d0 = (idx & 31) * 4;
        float4 q = *(const float4*)(Qb + m * DIM + d0);
        *(float2*)&Qs2[(d0+0)*132 + 2*m] = make_float2(q.x, q.x);
        *(float2*)&Qs2[(d0+1)*132 + 2*m] = make_float2(q.y, q.y);
        *(float2*)&Qs2[(d0+2)*132 + 2*m] = make_float2(q.z, q.z);
        *(float2*)&Qs2[(d0+3)*132 + 2*m] = make_float2(q.w, q.w);
    }

    unsigned long long Od[4][4];
    #pragma unroll
    for (int i = 0; i < 4; i++)
        #pragma unroll
        for (int j = 0; j < 4; j++) Od[i][j] = 0ull;
    float den[4] = {0.f, 0.f, 0.f, 0.f};

    for (int kt = 0; kt <= qt; kt++) {
        __syncthreads();
        #pragma unroll
        for (int it = 0; it < 8; it++) {
            int idx = tid + it * 256;
            int n = idx >> 5, d0 = (idx & 31) * 4;
            float4 kv = *(const float4*)(Kb + (size_t)(kt * 64 + n) * DIM + d0);
            Ks[(d0+0)*66 + n] = kv.x;
            Ks[(d0+1)*66 + n] = kv.y;
            Ks[(d0+2)*66 + n] = kv.z;
            Ks[(d0+3)*66 + n] = kv.w;
            float4 vv = *(const float4*)(Vb + (size_t)(kt * 64 + n) * DIM + d0);
            *(float4*)&Vs[n * 132 + d0] = vv;
        }
        __syncthreads();

        unsigned long long S[4][2];
        #pragma unroll
        for (int i = 0; i < 4; i++) { S[i][0] = 0ull; S[i][1] = 0ull; }
        #pragma unroll 8
        for (int d = 0; d < 128; d++) {
            ulonglong2 qa = *(const ulonglong2*)&Qs2[d * 132 + 8 * ty];
            ulonglong2 qb = *(const ulonglong2*)&Qs2[d * 132 + 8 * ty + 4];
            unsigned long long k0 = *(const unsigned long long*)&Ks[d * 66 + 4 * tx];
            unsigned long long k1 = *(const unsigned long long*)&Ks[d * 66 + 4 * tx + 2];
            unsigned long long qv[4] = {qa.x, qa.y, qb.x, qb.y};
            #pragma unroll
            for (int i = 0; i < 4; i++) {
                fma2(S[i][0], qv[i], k0);
                fma2(S[i][1], qv[i], k1);
            }
        }

        const bool diag = (kt == qt);
        #pragma unroll
        for (int i = 0; i < 4; i++) {
            const int m = ty * 4 + i;
            const int qglob = qt * 64 + m;
            float rs = 0.f;
            #pragma unroll
            for (int jp = 0; jp < 2; jp++) {
                const int n = tx * 4 + jp * 2;
                float slo = f2lo(S[i][jp]) * SCALE_QK;
                float shi = f2hi(S[i][jp]) * SCALE_QK;
                float plo = __expf(SOFTCAP * tanhf(slo * (1.0f / SOFTCAP)));
                float phi = __expf(SOFTCAP * tanhf(shi * (1.0f / SOFTCAP)));
                if (diag) {
                    if (kt * 64 + n     > qglob) plo = 0.f;
                    if (kt * 64 + n + 1 > qglob) phi = 0.f;
                }
                rs += plo + phi;
                *(float2*)&Ps2[(n    ) * 132 + 2 * m] = make_float2(plo, plo);
                *(float2*)&Ps2[(n + 1) * 132 + 2 * m] = make_float2(phi, phi);
            }
            rs += __shfl_xor_sync(0xffffffffu, rs, 1);
            rs += __shfl_xor_sync(0xffffffffu, rs, 2);
            rs += __shfl_xor_sync(0xffffffffu, rs, 4);
            rs += __shfl_xor_sync(0xffffffffu, rs, 8);
            den[i] += rs;
        }
        __syncthreads();

        #pragma unroll 4
        for (int k = 0; k < 64; k++) {
            ulonglong2 pa = *(const ulonglong2*)&Ps2[k * 132 + 8 * ty];
            ulonglong2 pb = *(const ulonglong2*)&Ps2[k * 132 + 8 * ty + 4];
            ulonglong2 v0 = *(const ulonglong2*)&Vs[k * 132 + 8 * tx];
            ulonglong2 v1 = *(const ulonglong2*)&Vs[k * 132 + 8 * tx + 4];
            unsigned long long pv[4] = {pa.x, pa.y, pb.x, pb.y};
            unsigned long long vv[4] = {v0.x, v0.y, v1.x, v1.y};
            #pragma unroll
            for (int i = 0; i < 4; i++)
                #pragma unroll
                for (int j = 0; j < 4; j++)
                    fma2(Od[i][j], pv[i], vv[j]);
        }
    }

    float* Ob = g_at + (size_t)(b * TT + qt * 64 + ty * 4) * DIM + h * HD + tx * 8;
    #pragma unroll
    for (int i = 0; i < 4; i++) {
        float r = 1.0f / den[i];
        *(float4*)(Ob + i * DIM)     = make_float4(f2lo(Od[i][0]) * r, f2hi(Od[i][0]) * r,
                                                   f2lo(Od[i][1]) * r, f2hi(Od[i][1]) * r);
        *(float4*)(Ob + i * DIM + 4) = make_float4(f2lo(Od[i][2]) * r, f2hi(Od[i][2]) * r,
                                                   f2lo(Od[i][3]) * r, f2hi(Od[i][3]) * r);
    }
}

// ---------------------------- gate + residual blend ---------------------------
__global__ __launch_bounds__(256)
void blend_kernel(const float* __restrict__ x, const float* __restrict__ gb,
                  float* __restrict__ out)
{
    const int i4 = blockIdx.x * 256 + threadIdx.x;
    const int col4 = i4 & 511;
    float4 xv = ((const float4*)x)[i4];
    float4 ov = ((const float4*)g_op)[i4];
    float4 gv = ((const float4*)g_gl)[i4];
    float4 bv = ((const float4*)gb)[col4];
    float a0 = 1.0f / (1.0f + __expf(-(gv.x + bv.x)));
    float a1 = 1.0f / (1.0f + __expf(-(gv.y + bv.y)));
    float a2 = 1.0f / (1.0f + __expf(-(gv.z + bv.z)));
    float a3 = 1.0f / (1.0f + __expf(-(gv.w + bv.w)));
    float4 r;
    r.x = xv.x + a0 * (ov.x - xv.x);
    r.y = xv.y + a1 * (ov.y - xv.y);
    r.z = xv.z + a2 * (ov.z - xv.z);
    r.w = xv.w + a3 * (ov.w - xv.w);
    ((float4*)out)[i4] = r;
}

// ----------------------------------- launch -----------------------------------
extern "C" void kernel_launch(void* const* d_in, const int* in_sizes, int n_in,
                              void* d_out, int out_size)
{
    (void)in_sizes; (void)n_in; (void)out_size;
    const float* x   = (const float*)d_in[0];
    const float* Wq  = (const float*)d_in[2];
    const float* Wk  = (const float*)d_in[3];
    const float* Wv  = (const float*)d_in[4];
    const float* Wo  = (const float*)d_in[5];
    const float* lnw = (const float*)d_in[6];
    const float* gW  = (const float*)d_in[7];
    const float* gb  = (const float*)d_in[8];
    float* out = (float*)d_out;

    static int attr_set = 0;
    if (!attr_set) {
        cudaFuncSetAttribute(attn_kernel, cudaFuncAttributeMaxDynamicSharedMemorySize, ATT_SMEM_BYTES);
        cudaFuncSetAttribute(mma_gemm_kernel, cudaFuncAttributeMaxDynamicSharedMemorySize, GEMM_SMEM);
        attr_set = 1;
    }

    void *pq, *pk, *pv, *pat, *pop, *pgl, *pxn3, *px3, *pat3, *pw3;
    cudaGetSymbolAddress(&pq,  g_q);
    cudaGetSymbolAddress(&pk,  g_k);
    cudaGetSymbolAddress(&pv,  g_v);
    cudaGetSymbolAddress(&pat, g_at);
    cudaGetSymbolAddress(&pop, g_op);
    cudaGetSymbolAddress(&pgl, g_gl);
    cudaGetSymbolAddress(&pxn3, g_xn3);
    cudaGetSymbolAddress(&px3,  g_x3);
    cudaGetSymbolAddress(&pat3, g_at3);
    cudaGetSymbolAddress(&pw3,  g_w3);
    __nv_bfloat16* w3 = (__nv_bfloat16*)pw3;
    const size_t WSTRIDE = (size_t)DIM * K3;

    // conversions
    rmsnorm_split_kernel<<<MTOT, 256>>>(x, lnw);
    convert_split_kernel<<<(MTOT * (DIM/4)) / 256, 256>>>(x, (__nv_bfloat16*)px3, 1);
    convert_split_kernel<<<(DIM  * (DIM/4)) / 256, 256>>>(Wq, w3 + 0 * WSTRIDE, 0);
    convert_split_kernel<<<(DIM  * (DIM/4)) / 256, 256>>>(Wk, w3 + 1 * WSTRIDE, 0);
    convert_split_kernel<<<(DIM  * (DIM/4)) / 256, 256>>>(Wv, w3 + 2 * WSTRIDE, 0);
    convert_split_kernel<<<(DIM  * (DIM/4)) / 256, 256>>>(Wo, w3 + 3 * WSTRIDE, 0);
    convert_split_kernel<<<(DIM  * (DIM/4)) / 256, 256>>>(gW, w3 + 4 * WSTRIDE, 0);

    dim3 gGemm(DIM / BN, MTOT / BM);   // (16, 32)
    mma_gemm_kernel<<<gGemm, 256, GEMM_SMEM>>>((const __nv_bfloat16*)pxn3, w3 + 0 * WSTRIDE, (float*)pq, DIM);
    mma_gemm_kernel<<<gGemm, 256, GEMM_SMEM>>>((const __nv_bfloat16*)pxn3, w3 + 1 * WSTRIDE, (float*)pk, DIM);
    mma_gemm_kernel<<<gGemm, 256, GEMM_SMEM>>>((const __nv_bfloat16*)pxn3, w3 + 2 * WSTRIDE, (float*)pv, DIM);
    mma_gemm_kernel<<<gGemm, 256, GEMM_SMEM>>>((const __nv_bfloat16*)px3,  w3 + 4 * WSTRIDE, (float*)pgl, DIM);

    dim3 gAttn(TT / 64, NH, BB);
    attn_kernel<<<gAttn, 256, ATT_SMEM_BYTES>>>();

    convert_split_kernel<<<(MTOT * (DIM/4)) / 256, 256>>>((const float*)pat, (__nv_bfloat16*)pat3, 1);
    mma_gemm_kernel<<<gGemm, 256, GEMM_SMEM>>>((const __nv_bfloat16*)pat3, w3 + 3 * WSTRIDE, (float*)pop, DIM);

    blend_kernel<<<(MTOT * DIM / 4) / 256, 256>>>(x, gb, out);
}

// round 7
// speedup vs baseline: 7.5370x; 2.0382x over previous
#include <cuda_runtime.h>
#include <cuda_bf16.h>
#include <math.h>
#include <stdint.h>

#define BB   2
#define TT   2048
#define DIM  2048
#define NH   16
#define HD   128
#define MTOT (BB*TT)
#define K3   6144
#define SCALE_QK 0.08838834764831843f
#define SOFTCAP 30.0f

// ---------------- scratch ----------------
__device__ float g_q [MTOT * DIM];
__device__ float g_k [MTOT * DIM];
__device__ float g_v [MTOT * DIM];
__device__ float g_op[MTOT * DIM];
__device__ float g_gl[MTOT * DIM];
__device__ __nv_bfloat16 g_xn3[(size_t)MTOT * K3];
__device__ __nv_bfloat16 g_x3 [(size_t)MTOT * K3];
__device__ __nv_bfloat16 g_at3[(size_t)MTOT * K3];
__device__ __nv_bfloat16 g_w3[5][(size_t)DIM * K3];
__device__ __nv_bfloat16 g_qb[(size_t)MTOT * DIM];
__device__ __nv_bfloat16 g_kb[(size_t)MTOT * DIM];
__device__ __nv_bfloat16 g_vb[(size_t)MTOT * DIM];

// ---------------- helpers ----------------
__device__ __forceinline__ uint32_t smem_u32(const void* p) {
    uint32_t a;
    asm("{ .reg .u64 t; cvta.to.shared.u64 t, %1; cvt.u32.u64 %0, t; }" : "=r"(a) : "l"(p));
    return a;
}

#define LDSM_X4(r0, r1, r2, r3, a) \
    asm volatile("ldmatrix.sync.aligned.m8n8.x4.shared.b16 {%0,%1,%2,%3}, [%4];" \
        : "=r"(r0), "=r"(r1), "=r"(r2), "=r"(r3) : "r"(a))
#define LDSM_X4_T(r0, r1, r2, r3, a) \
    asm volatile("ldmatrix.sync.aligned.m8n8.x4.trans.shared.b16 {%0,%1,%2,%3}, [%4];" \
        : "=r"(r0), "=r"(r1), "=r"(r2), "=r"(r3) : "r"(a))
#define MMA_BF16(c, a0, a1, a2, a3, b0, b1) \
    asm volatile("mma.sync.aligned.m16n8k16.row.col.f32.bf16.bf16.f32 " \
        "{%0,%1,%2,%3}, {%4,%5,%6,%7}, {%8,%9}, {%0,%1,%2,%3};" \
        : "+f"((c)[0]), "+f"((c)[1]), "+f"((c)[2]), "+f"((c)[3]) \
        : "r"(a0), "r"(a1), "r"(a2), "r"(a3), "r"(b0), "r"(b1))

__device__ __forceinline__ void bsplit(float v, unsigned short &h, unsigned short &l) {
    __nv_bfloat16 hb = __float2bfloat16_rn(v);
    __nv_bfloat16 lb = __float2bfloat16_rn(v - __bfloat162float(hb));
    h = __bfloat16_as_ushort(hb);
    l = __bfloat16_as_ushort(lb);
}
__device__ __forceinline__ uint32_t packbf(float lo, float hi) {
    __nv_bfloat162 b = __floats2bfloat162_rn(lo, hi);
    return *(uint32_t*)&b;
}

// ------------- RMSNorm fused with bf16 split ([hi|hi|lo]) -------------
__global__ __launch_bounds__(256)
void rmsnorm_split_kernel(const float* __restrict__ x, const float* __restrict__ w)
{
    const int row = blockIdx.x;
    const int tid = threadIdx.x;
    const float4* xr = (const float4*)(x + (size_t)row * DIM);
    float4 v0 = xr[tid];
    float4 v1 = xr[tid + 256];
    float s = v0.x*v0.x + v0.y*v0.y + v0.z*v0.z + v0.w*v0.w
            + v1.x*v1.x + v1.y*v1.y + v1.z*v1.z + v1.w*v1.w;
    #pragma unroll
    for (int o = 16; o > 0; o >>= 1) s += __shfl_xor_sync(0xffffffffu, s, o);
    __shared__ float red[8];
    if ((tid & 31) == 0) red[tid >> 5] = s;
    __syncthreads();
    float tot = red[0]+red[1]+red[2]+red[3]+red[4]+red[5]+red[6]+red[7];
    float r = rsqrtf(tot * (1.0f / (float)DIM) + 1e-6f);
    const float4* wr = (const float4*)w;
    float4 w0 = wr[tid], w1 = wr[tid + 256];
    float y[8] = { v0.x*r*w0.x, v0.y*r*w0.y, v0.z*r*w0.z, v0.w*r*w0.w,
                   v1.x*r*w1.x, v1.y*r*w1.y, v1.z*r*w1.z, v1.w*r*w1.w };
    unsigned short* ob = (unsigned short*)g_xn3 + (size_t)row * K3;
    #pragma unroll
    for (int half = 0; half < 2; half++) {
        unsigned short h[4], l[4];
        bsplit(y[half*4+0], h[0], l[0]); bsplit(y[half*4+1], h[1], l[1]);
        bsplit(y[half*4+2], h[2], l[2]); bsplit(y[half*4+3], h[3], l[3]);
        ushort4 hs = make_ushort4(h[0], h[1], h[2], h[3]);
        ushort4 ls = make_ushort4(l[0], l[1], l[2], l[3]);
        int c = (tid + half * 256) * 4;
        *(ushort4*)(ob + c)        = hs;
        *(ushort4*)(ob + c + 2048) = hs;
        *(ushort4*)(ob + c + 4096) = ls;
    }
}

// ------------- split conversion: [R,2048] fp32 -> [R,6144] bf16 -------------
// modeA=1: [hi|hi|lo]   modeA=0: [hi|lo|hi]
__global__ __launch_bounds__(256)
void convert_split_kernel(const float* __restrict__ in, __nv_bfloat16* __restrict__ out, int modeA)
{
    int idx = blockIdx.x * 256 + threadIdx.x;
    float4 v = ((const float4*)in)[idx];
    int r = idx >> 9, c = (idx & 511) * 4;
    unsigned short h[4], l[4];
    bsplit(v.x, h[0], l[0]); bsplit(v.y, h[1], l[1]);
    bsplit(v.z, h[2], l[2]); bsplit(v.w, h[3], l[3]);
    ushort4 hs = make_ushort4(h[0], h[1], h[2], h[3]);
    ushort4 ls = make_ushort4(l[0], l[1], l[2], l[3]);
    unsigned short* ob = (unsigned short*)out + (size_t)r * K3 + c;
    *(ushort4*)(ob)        = hs;
    *(ushort4*)(ob + 2048) = modeA ? hs : ls;
    *(ushort4*)(ob + 4096) = modeA ? ls : hs;
}

// ------------- q/k/v fp32 [b,t,h*d] -> bf16 [b,h,t,d] -------------
__global__ __launch_bounds__(256)
void qkv_to_bf16_kernel()
{
    const float* in;
    __nv_bfloat16* outp;
    if (blockIdx.y == 0)      { in = g_q; outp = g_qb; }
    else if (blockIdx.y == 1) { in = g_k; outp = g_kb; }
    else                      { in = g_v; outp = g_vb; }
    int i = blockIdx.x * 256 + threadIdx.x;
    int o = i * 4;
    int d = o & 127;
    int t = (o >> 7) & 2047;
    int h = (o >> 18) & 15;
    int b = o >> 22;
    float4 v = *(const float4*)(in + ((size_t)(b * 2048 + t)) * 2048 + h * 128 + d);
    ushort4 s;
    s.x = __bfloat16_as_ushort(__float2bfloat16_rn(v.x));
    s.y = __bfloat16_as_ushort(__float2bfloat16_rn(v.y));
    s.z = __bfloat16_as_ushort(__float2bfloat16_rn(v.z));
    s.w = __bfloat16_as_ushort(__float2bfloat16_rn(v.w));
    *(ushort4*)((unsigned short*)outp + ((size_t)((b * 16 + h) * 2048 + t)) * 128 + d) = s;
}

// ------------- HMMA bf16 GEMM: C[M,2048] = A'[M,6144] * B'[2048,6144]^T -------------
#define BM 128
#define BN 128
#define BK 64
#define GSTAGES 3
#define NCHUNK (K3 / BK)                    // 96
#define CHUNK_BYTES (BM*128 + BN*128)       // 32768
#define GEMM_SMEM (GSTAGES * CHUNK_BYTES + 1024)

__global__ __launch_bounds__(256, 2)
void mma_gemm_kernel(const __nv_bfloat16* __restrict__ A,
                     const __nv_bfloat16* __restrict__ B,
                     float* __restrict__ C, int N)
{
    extern __shared__ char dynsm[];
    const uint32_t sb = (smem_u32(dynsm) + 1023u) & ~1023u;
    const int tid = threadIdx.x;
    const int w = tid >> 5, lane = tid & 31;
    const int wm = (w >> 2) * 64, wn = (w & 3) * 32;

    const int mBase = blockIdx.y * BM;
    const int nBase = blockIdx.x * BN;
    const __nv_bfloat16* Ab = A + (size_t)mBase * K3;
    const __nv_bfloat16* Bb = B + (size_t)nBase * K3;

    float acc[4][4][4];
    #pragma unroll
    for (int i = 0; i < 4; i++)
        #pragma unroll
        for (int j = 0; j < 4; j++)
            #pragma unroll
            for (int q = 0; q < 4; q++) acc[i][j][q] = 0.f;

    auto load_chunk = [&](int c, int stage) {
        uint32_t abase = sb + stage * CHUNK_BYTES;
        uint32_t bbase = abase + BM * 128;
        #pragma unroll
        for (int t = 0; t < 8; t++) {
            int o = tid + t * 256;
            const __nv_bfloat16* src;
            uint32_t base;
            int row, c16;
            if (o < 1024) {
                row = o >> 3; c16 = o & 7;
                src = Ab + (size_t)row * K3 + c * 64 + c16 * 8;
                base = abase;
            } else {
                int ob = o - 1024;
                row = ob >> 3; c16 = ob & 7;
                src = Bb + (size_t)row * K3 + c * 64 + c16 * 8;
                base = bbase;
            }
            uint32_t off = (uint32_t)(row * 128 + c16 * 16);
            uint32_t dst = base + (off ^ ((off >> 3) & 0x70));
            asm volatile("cp.async.cg.shared.global [%0], [%1], 16;" :: "r"(dst), "l"(src) : "memory");
        }
        asm volatile("cp.async.commit_group;" ::: "memory");
    };

    load_chunk(0, 0);
    load_chunk(1, 1);

    const int r8 = lane & 7;
    const int mi = lane >> 3;
    const int rowadd = r8 + (mi & 1) * 8;
    const int colmi = (mi >> 1) * 16;

    #pragma unroll 1
    for (int c = 0; c < NCHUNK; c++) {
        asm volatile("cp.async.wait_group %0;" :: "n"(1));
        __syncthreads();
        if (c + 2 < NCHUNK) load_chunk(c + 2, (c + 2) % GSTAGES);
        else asm volatile("cp.async.commit_group;" ::: "memory");

        uint32_t abase = sb + (c % GSTAGES) * CHUNK_BYTES;
        uint32_t bbase = abase + BM * 128;

        #pragma unroll
        for (int s = 0; s < 4; s++) {
            const int colb = s * 32 + colmi;
            uint32_t af[4][4];
            #pragma unroll
            for (int i = 0; i < 4; i++) {
                uint32_t off = (uint32_t)((wm + i * 16 + rowadd) * 128 + colb);
                uint32_t addr = abase + (off ^ ((off >> 3) & 0x70));
                LDSM_X4(af[i][0], af[i][1], af[i][2], af[i][3], addr);
            }
            uint32_t bf[2][4];
            #pragma unroll
            for (int j = 0; j < 2; j++) {
                uint32_t off = (uint32_t)((wn + j * 16 + rowadd) * 128 + colb);
                uint32_t addr = bbase + (off ^ ((off >> 3) & 0x70));
                LDSM_X4(bf[j][0], bf[j][1], bf[j][2], bf[j][3], addr);
            }
            #pragma unroll
            for (int i = 0; i < 4; i++)
                #pragma unroll
                for (int j = 0; j < 2; j++)
                    #pragma unroll
                    for (int ns = 0; ns < 2; ns++)
                        MMA_BF16(acc[i][j * 2 + ns],
                                 af[i][0], af[i][1], af[i][2], af[i][3],
                                 bf[j][ns], bf[j][2 + ns]);
        }
    }

    const int gid = lane >> 2, ctg = lane & 3;
    float* Cw = C + (size_t)(mBase + wm + gid) * N + nBase + wn + ctg * 2;
    #pragma unroll
    for (int i = 0; i < 4; i++)
        #pragma unroll
        for (int jn = 0; jn < 4; jn++) {
            float* p = Cw + (size_t)(i * 16) * N + jn * 8;
            *(float2*)p             = make_float2(acc[i][jn][0], acc[i][jn][1]);
            *(float2*)(p + 8 * N)   = make_float2(acc[i][jn][2], acc[i][jn][3]);
        }
}

// ------------- HMMA causal softcapped flash attention (BQ=128, BK=64) -------------
// smem: Q[128][136] + 2 stages of (K[64][136] + V[64][136]); bf16, 272B rows.
#define AST 136
#define KV_BYTES (2 * 64 * AST * 2)            // K+V one stage = 34816
#define ATT2_SMEM (128 * AST * 2 + 2 * KV_BYTES)  // 104448

__global__ __launch_bounds__(256)
void attn_mma_kernel(const __nv_bfloat16* __restrict__ Qg,
                     const __nv_bfloat16* __restrict__ Kg,
                     const __nv_bfloat16* __restrict__ Vg)
{
    extern __shared__ char smraw[];
    const uint32_t sQ  = smem_u32(smraw);
    const uint32_t sKV = sQ + 128 * AST * 2;

    const int tid = threadIdx.x;
    const int w = tid >> 5, lane = tid & 31;
    const int qt = (int)gridDim.x - 1 - (int)blockIdx.x;
    const int h  = blockIdx.y;
    const int b  = blockIdx.z;

    const __nv_bfloat16* Qb = Qg + ((size_t)(b * NH + h) * TT + qt * 128) * HD;
    const __nv_bfloat16* Kb = Kg + ((size_t)(b * NH + h) * TT) * HD;
    const __nv_bfloat16* Vb = Vg + ((size_t)(b * NH + h) * TT) * HD;

    // Q load: 128 rows x 256B (16 chunks of 16B per row)
    #pragma unroll
    for (int t = 0; t < 8; t++) {
        int ch = tid + t * 256;
        int row = ch >> 4, c16 = ch & 15;
        uint32_t dst = sQ + row * 272 + c16 * 16;
        const __nv_bfloat16* src = Qb + row * 128 + c16 * 8;
        asm volatile("cp.async.cg.shared.global [%0], [%1], 16;" :: "r"(dst), "l"(src) : "memory");
    }
    asm volatile("cp.async.commit_group;" ::: "memory");

    auto loadKV = [&](int kt, int stage) {
        uint32_t base = sKV + stage * KV_BYTES;
        const __nv_bfloat16* Kt = Kb + (size_t)kt * 64 * HD;
        const __nv_bfloat16* Vt = Vb + (size_t)kt * 64 * HD;
        #pragma unroll
        for (int t = 0; t < 8; t++) {
            int ch = tid + t * 256;
            int row = (ch >> 4) & 63, c16 = ch & 15;
            bool isV = ch >= 1024;
            const __nv_bfloat16* src = (isV ? Vt : Kt) + row * 128 + c16 * 8;
            uint32_t dst = base + (isV ? (64u * 272u) : 0u) + row * 272 + c16 * 16;
            asm volatile("cp.async.cg.shared.global [%0], [%1], 16;" :: "r"(dst), "l"(src) : "memory");
        }
        asm volatile("cp.async.commit_group;" ::: "memory");
    };

    const int numK = 2 * qt + 2;
    loadKV(0, 0);
    loadKV(1, 1);

    float oacc[16][4];
    #pragma unroll
    for (int j = 0; j < 16; j++)
        #pragma unroll
        for (int q = 0; q < 4; q++) oacc[j][q] = 0.f;
    float den0 = 0.f, den1 = 0.f;

    const int rowadd = (lane & 7) + ((lane >> 3) & 1) * 8;
    const int colmi  = (lane >> 4) * 16;          // bytes
    const int colq   = (lane & 3) * 2;
    const int rr0    = qt * 128 + w * 16 + (lane >> 2);

    #pragma unroll 1
    for (int kt = 0; kt < numK; kt++) {
        asm volatile("cp.async.wait_group %0;" :: "n"(1));
        __syncthreads();
        const uint32_t sK = sKV + (kt & 1) * KV_BYTES;
        const uint32_t sV = sK + 64u * 272u;

        // ---- S = Q K^T ----
        float cs[8][4];
        #pragma unroll
        for (int j = 0; j < 8; j++)
            #pragma unroll
            for (int q = 0; q < 4; q++) cs[j][q] = 0.f;

        #pragma unroll
        for (int s = 0; s < 8; s++) {
            uint32_t a0, a1, a2, a3;
            LDSM_X4(a0, a1, a2, a3, sQ + (w * 16 + rowadd) * 272 + s * 32 + colmi);
            #pragma unroll
            for (int g = 0; g < 4; g++) {
                uint32_t k0, k1, k2, k3;
                LDSM_X4(k0, k1, k2, k3, sK + (g * 16 + rowadd) * 272 + s * 32 + colmi);
                MMA_BF16(cs[2*g],   a0, a1, a2, a3, k0, k2);
                MMA_BF16(cs[2*g+1], a0, a1, a2, a3, k1, k3);
            }
        }

        // ---- softcap + exp + causal mask + row-sum ----
        const bool msk = (kt >= 2 * qt);
        #pragma unroll
        for (int j = 0; j < 8; j++) {
            const int cb = kt * 64 + j * 8 + colq;
            #pragma unroll
            for (int q = 0; q < 4; q++) {
                float sv = cs[j][q] * SCALE_QK;
                float xx = sv * (1.0f / SOFTCAP);
                float x2 = xx * xx;
                float capped;
                if (fabsf(xx) > 0.55f) capped = SOFTCAP * tanhf(xx);
                else capped = sv * (1.0f - x2 * (0.33333334f - x2 * (0.13333334f - x2 * 0.05396825f)));
                float p = __expf(capped);
                if (msk) {
                    int col = cb + (q & 1);
                    int rowg = rr0 + (q >> 1) * 8;
                    if (col > rowg) p = 0.f;
                }
                cs[j][q] = p;
                if (q >> 1) den1 += p; else den0 += p;
            }
        }

        // ---- pack P C-fragments into A-fragments ----
        uint32_t pa[4][4];
        #pragma unroll
        for (int kk = 0; kk < 4; kk++) {
            pa[kk][0] = packbf(cs[2*kk][0],   cs[2*kk][1]);
            pa[kk][1] = packbf(cs[2*kk][2],   cs[2*kk][3]);
            pa[kk][2] = packbf(cs[2*kk+1][0], cs[2*kk+1][1]);
            pa[kk][3] = packbf(cs[2*kk+1][2], cs[2*kk+1][3]);
        }

        // ---- O += P V ----
        #pragma unroll
        for (int kk = 0; kk < 4; kk++) {
            #pragma unroll
            for (int g = 0; g < 8; g++) {
                uint32_t v0, v1, v2, v3;
                LDSM_X4_T(v0, v1, v2, v3, sV + (kk * 16 + rowadd) * 272 + g * 32 + colmi);
                MMA_BF16(oacc[2*g],   pa[kk][0], pa[kk][1], pa[kk][2], pa[kk][3], v0, v1);
                MMA_BF16(oacc[2*g+1], pa[kk][0], pa[kk][1], pa[kk][2], pa[kk][3], v2, v3);
            }
        }

        __syncthreads();
        if (kt + 2 < numK) loadKV(kt + 2, kt & 1);
        else asm volatile("cp.async.commit_group;" ::: "memory");
    }

    // ---- epilogue: normalize + split-bf16 write to g_at3 ([hi|hi|lo]) ----
    den0 += __shfl_xor_sync(0xffffffffu, den0, 1);
    den0 += __shfl_xor_sync(0xffffffffu, den0, 2);
    den1 += __shfl_xor_sync(0xffffffffu, den1, 1);
    den1 += __shfl_xor_sync(0xffffffffu, den1, 2);
    const float i0 = 1.0f / den0, i1 = 1.0f / den1;

    const int t0 = qt * 128 + w * 16 + (lane >> 2);
    unsigned short* outb = (unsigned short*)g_at3;
    size_t base0 = ((size_t)(b * TT + t0)) * K3 + h * 128 + colq;
    size_t base1 = base0 + (size_t)8 * K3;
    #pragma unroll
    for (int j = 0; j < 16; j++) {
        float p0 = oacc[j][0] * i0, p1 = oacc[j][1] * i0;
        float p2 = oacc[j][2] * i1, p3 = oacc[j][3] * i1;
        unsigned short h0, l0, h1, l1, h2, l2, h3, l3;
        bsplit(p0, h0, l0); bsplit(p1, h1, l1);
        bsplit(p2, h2, l2); bsplit(p3, h3, l3);
        unsigned short* q0 = outb + base0 + j * 8;
        unsigned short* q1 = outb + base1 + j * 8;
        *(ushort2*)(q0)        = make_ushort2(h0, h1);
        *(ushort2*)(q0 + 2048) = make_ushort2(h0, h1);
        *(ushort2*)(q0 + 4096) = make_ushort2(l0, l1);
        *(ushort2*)(q1)        = make_ushort2(h2, h3);
        *(ushort2*)(q1 + 2048) = make_ushort2(h2, h3);
        *(ushort2*)(q1 + 4096) = make_ushort2(l2, l3);
    }
}

// ---------------------------- gate + residual blend ---------------------------
__global__ __launch_bounds__(256)
void blend_kernel(const float* __restrict__ x, const float* __restrict__ gb,
                  float* __restrict__ out)
{
    const int i4 = blockIdx.x * 256 + threadIdx.x;
    const int col4 = i4 & 511;
    float4 xv = ((const float4*)x)[i4];
    float4 ov = ((const float4*)g_op)[i4];
    float4 gv = ((const float4*)g_gl)[i4];
    float4 bv = ((const float4*)gb)[col4];
    float a0 = 1.0f / (1.0f + __expf(-(gv.x + bv.x)));
    float a1 = 1.0f / (1.0f + __expf(-(gv.y + bv.y)));
    float a2 = 1.0f / (1.0f + __expf(-(gv.z + bv.z)));
    float a3 = 1.0f / (1.0f + __expf(-(gv.w + bv.w)));
    float4 r;
    r.x = xv.x + a0 * (ov.x - xv.x);
    r.y = xv.y + a1 * (ov.y - xv.y);
    r.z = xv.z + a2 * (ov.z - xv.z);
    r.w = xv.w + a3 * (ov.w - xv.w);
    ((float4*)out)[i4] = r;
}

// ----------------------------------- launch -----------------------------------
extern "C" void kernel_launch(void* const* d_in, const int* in_sizes, int n_in,
                              void* d_out, int out_size)
{
    (void)in_sizes; (void)n_in; (void)out_size;
    const float* x   = (const float*)d_in[0];
    const float* Wq  = (const float*)d_in[2];
    const float* Wk  = (const float*)d_in[3];
    const float* Wv  = (const float*)d_in[4];
    const float* Wo  = (const float*)d_in[5];
    const float* lnw = (const float*)d_in[6];
    const float* gW  = (const float*)d_in[7];
    const float* gb  = (const float*)d_in[8];
    float* out = (float*)d_out;

    static int attr_set = 0;
    if (!attr_set) {
        cudaFuncSetAttribute(mma_gemm_kernel, cudaFuncAttributeMaxDynamicSharedMemorySize, GEMM_SMEM);
        cudaFuncSetAttribute(attn_mma_kernel, cudaFuncAttributeMaxDynamicSharedMemorySize, ATT2_SMEM);
        attr_set = 1;
    }

    void *pq, *pk, *pv, *pop, *pgl, *pxn3, *px3, *pat3, *pw3, *pqb, *pkb, *pvb;
    cudaGetSymbolAddress(&pq,  g_q);
    cudaGetSymbolAddress(&pk,  g_k);
    cudaGetSymbolAddress(&pv,  g_v);
    cudaGetSymbolAddress(&pop, g_op);
    cudaGetSymbolAddress(&pgl, g_gl);
    cudaGetSymbolAddress(&pxn3, g_xn3);
    cudaGetSymbolAddress(&px3,  g_x3);
    cudaGetSymbolAddress(&pat3, g_at3);
    cudaGetSymbolAddress(&pw3,  g_w3);
    cudaGetSymbolAddress(&pqb, g_qb);
    cudaGetSymbolAddress(&pkb, g_kb);
    cudaGetSymbolAddress(&pvb, g_vb);
    __nv_bfloat16* w3 = (__nv_bfloat16*)pw3;
    const size_t WSTRIDE = (size_t)DIM * K3;

    // conversions
    rmsnorm_split_kernel<<<MTOT, 256>>>(x, lnw);
    convert_split_kernel<<<(MTOT * (DIM/4)) / 256, 256>>>(x, (__nv_bfloat16*)px3, 1);
    convert_split_kernel<<<(DIM  * (DIM/4)) / 256, 256>>>(Wq, w3 + 0 * WSTRIDE, 0);
    convert_split_kernel<<<(DIM  * (DIM/4)) / 256, 256>>>(Wk, w3 + 1 * WSTRIDE, 0);
    convert_split_kernel<<<(DIM  * (DIM/4)) / 256, 256>>>(Wv, w3 + 2 * WSTRIDE, 0);
    convert_split_kernel<<<(DIM  * (DIM/4)) / 256, 256>>>(Wo, w3 + 3 * WSTRIDE, 0);
    convert_split_kernel<<<(DIM  * (DIM/4)) / 256, 256>>>(gW, w3 + 4 * WSTRIDE, 0);

    dim3 gGemm(DIM / BN, MTOT / BM);   // (16, 32)
    mma_gemm_kernel<<<gGemm, 256, GEMM_SMEM>>>((const __nv_bfloat16*)pxn3, w3 + 0 * WSTRIDE, (float*)pq, DIM);
    mma_gemm_kernel<<<gGemm, 256, GEMM_SMEM>>>((const __nv_bfloat16*)pxn3, w3 + 1 * WSTRIDE, (float*)pk, DIM);
    mma_gemm_kernel<<<gGemm, 256, GEMM_SMEM>>>((const __nv_bfloat16*)pxn3, w3 + 2 * WSTRIDE, (float*)pv, DIM);
    mma_gemm_kernel<<<gGemm, 256, GEMM_SMEM>>>((const __nv_bfloat16*)px3,  w3 + 4 * WSTRIDE, (float*)pgl, DIM);

    // q/k/v -> bf16 [b,h,t,d]
    dim3 gConv((MTOT * DIM / 4) / 256, 3);
    qkv_to_bf16_kernel<<<gConv, 256>>>();

    dim3 gAttn(TT / 128, NH, BB);      // (16, 16, 2)
    attn_mma_kernel<<<gAttn, 256, ATT2_SMEM>>>((const __nv_bfloat16*)pqb,
                                               (const __nv_bfloat16*)pkb,
                                               (const __nv_bfloat16*)pvb);

    mma_gemm_kernel<<<gGemm, 256, GEMM_SMEM>>>((const __nv_bfloat16*)pat3, w3 + 3 * WSTRIDE, (float*)pop, DIM);

    blend_kernel<<<(MTOT * DIM / 4) / 256, 256>>>(x, gb, out);
}